// round 1
// baseline (speedup 1.0000x reference)
#include <cuda_runtime.h>
#include <math.h>

#define Bx 16
#define Tt 32
#define Nn 24
#define Kk 512
#define Hh 128
#define Vv 32000
#define NEGV -1000000000.0f
#define EPSV 1e-38f

// ---------------- device scratch (no allocation allowed) ----------------
__device__ __align__(16) float g_beta[Bx*Nn*Tt*Tt];
__device__ __align__(16) float g_alpha[Bx*Nn*Tt*Tt];
__device__ __align__(16) float g_et [Nn*Nn*Nn];   // [x][y][z]
__device__ __align__(16) float g_etY[Nn*Nn*Nn];   // [y][x][z]
__device__ __align__(16) float g_etZ[Nn*Nn*Nn];   // [z][x][y]
__device__ float g_tm;
__device__ __align__(16) float g_pnt[Bx*Tt*Nn];   // [(b*T+t)*N + n]

__device__ __forceinline__ int bidx(int b, int n, int i, int j) {
    return ((b*Nn + n)*Tt + i)*Tt + j;
}

// ---------------- init beta/alpha ----------------
__global__ void fill_kernel() {
    int idx = blockIdx.x*blockDim.x + threadIdx.x;
    if (idx < Bx*Nn*Tt*Tt) {
        g_beta[idx] = NEGV;
        int j = idx & 31;
        int i = (idx >> 5) & 31;
        int n = (idx >> 10) % Nn;
        g_alpha[idx] = (n == 0 && i == 0 && j == Tt-1) ? 0.0f : NEGV;
    }
}

// ---------------- theta: log_softmax rows + global max + 3 exp layouts ----------------
__global__ void theta_kernel(const float* __restrict__ Theta) {
    __shared__ float wmax[18];
    __shared__ float tm_s;
    int tid = threadIdx.x;              // 576 threads, one per (x,y) row
    const float* row = Theta + tid*Nn;
    float m = -3.4e38f;
    #pragma unroll
    for (int z = 0; z < Nn; z++) m = fmaxf(m, row[z]);
    float s = 0.f;
    #pragma unroll
    for (int z = 0; z < Nn; z++) s += expf(row[z] - m);
    float L = m + logf(s);
    float rm = m - L;                   // row max of theta_log
    #pragma unroll
    for (int off = 16; off > 0; off >>= 1)
        rm = fmaxf(rm, __shfl_xor_sync(0xffffffffu, rm, off));
    if ((tid & 31) == 0) wmax[tid >> 5] = rm;
    __syncthreads();
    if (tid == 0) {
        float t = -3.4e38f;
        for (int w = 0; w < 18; w++) t = fmaxf(t, wmax[w]);
        tm_s = t; g_tm = t;
    }
    __syncthreads();
    float tm = tm_s;
    int x = tid / Nn, y = tid % Nn;
    for (int z = 0; z < Nn; z++) {
        float e = expf(row[z] - L - tm);
        g_et [(x*Nn + y)*Nn + z] = e;
        g_etY[(y*Nn + x)*Nn + z] = e;
        g_etZ[(z*Nn + x)*Nn + y] = e;
    }
}

// ---------------- frontend: LN -> GELU MLP -> log_softmax -> beta diagonal ----------------
__global__ void frontend_kernel(const float* __restrict__ g_seq,
                                const float* __restrict__ ln_g,
                                const float* __restrict__ ln_b,
                                const float* __restrict__ W1,
                                const float* __restrict__ b1,
                                const float* __restrict__ W2,
                                const float* __restrict__ b2) {
    __shared__ float gs[Kk];
    __shared__ float red[Hh];
    __shared__ float hs[Hh];
    __shared__ float outs[Nn];
    int tid = threadIdx.x;              // 128 threads
    int t = blockIdx.x, b = blockIdx.y;
    const float* row = g_seq + (b*Tt + t)*Kk;

    float v0 = row[tid], v1 = row[tid+128], v2 = row[tid+256], v3 = row[tid+384];
    gs[tid] = v0; gs[tid+128] = v1; gs[tid+256] = v2; gs[tid+384] = v3;

    red[tid] = v0+v1+v2+v3; __syncthreads();
    for (int off = 64; off > 0; off >>= 1) { if (tid < off) red[tid] += red[tid+off]; __syncthreads(); }
    float mu = red[0] * (1.f/512.f);
    __syncthreads();
    red[tid] = v0*v0 + v1*v1 + v2*v2 + v3*v3; __syncthreads();
    for (int off = 64; off > 0; off >>= 1) { if (tid < off) red[tid] += red[tid+off]; __syncthreads(); }
    float var = red[0] * (1.f/512.f) - mu*mu;
    float rstd = rsqrtf(var + 1e-5f);
    __syncthreads();

    #pragma unroll
    for (int q = 0; q < 4; q++) {
        int k = tid + q*128;
        gs[k] = (gs[k] - mu) * rstd * ln_g[k] + ln_b[k];
    }
    __syncthreads();

    float acc = b1[tid];
    for (int k = 0; k < Kk; k++) acc = fmaf(gs[k], W1[k*Hh + tid], acc);
    hs[tid] = 0.5f * acc * (1.0f + erff(acc * 0.70710678118654752440f));
    __syncthreads();

    if (tid < Nn) {
        float o = b2[tid];
        for (int m2 = 0; m2 < Hh; m2++) o = fmaf(hs[m2], W2[m2*Nn + tid], o);
        outs[tid] = o;
    }
    __syncthreads();
    if (tid < Nn) {
        float m = -3.4e38f;
        #pragma unroll
        for (int n = 0; n < Nn; n++) m = fmaxf(m, outs[n]);
        float s = 0.f;
        #pragma unroll
        for (int n = 0; n < Nn; n++) s += expf(outs[n] - m);
        g_beta[bidx(b, tid, t, t)] = outs[tid] - m - logf(s);
    }
}

// ---------------- inside step (one per length l) ----------------
__global__ void inside_kernel(int l) {
    __shared__ float el_s[Nn*33];
    __shared__ float er_s[Nn*33];
    __shared__ float ml_s[32];
    __shared__ float mr_s[32];
    __shared__ float sc_s[Nn*33];
    int tid = threadIdx.x;               // 128
    int i = blockIdx.x, b = blockIdx.y;
    int S = l - 1, j = i + l - 1;

    for (int t = tid; t < Nn*S; t += 128) {
        int y = t % Nn, s = t / Nn;
        el_s[y*33 + s] = g_beta[bidx(b, y, i, i+s)];
        er_s[y*33 + s] = g_beta[bidx(b, y, i+s+1, j)];
    }
    __syncthreads();
    if (tid < S) {
        float m = -3.4e38f;
        #pragma unroll
        for (int y = 0; y < Nn; y++) m = fmaxf(m, el_s[y*33 + tid]);
        ml_s[tid] = m;
        #pragma unroll
        for (int y = 0; y < Nn; y++) el_s[y*33 + tid] = expf(el_s[y*33 + tid] - m);
        m = -3.4e38f;
        #pragma unroll
        for (int y = 0; y < Nn; y++) m = fmaxf(m, er_s[y*33 + tid]);
        mr_s[tid] = m;
        #pragma unroll
        for (int y = 0; y < Nn; y++) er_s[y*33 + tid] = expf(er_s[y*33 + tid] - m);
    }
    __syncthreads();

    for (int it = tid; it < Nn*S; it += 128) {
        int x = it / S, s = it - x*S;    // lanes share x -> uniform et loads
        float er_r[Nn];
        #pragma unroll
        for (int z = 0; z < Nn; z++) er_r[z] = er_s[z*33 + s];
        float acc = 0.f;
        #pragma unroll
        for (int y = 0; y < Nn; y++) {
            float c = el_s[y*33 + s];
            const float4* ep = reinterpret_cast<const float4*>(g_et + (x*Nn + y)*Nn);
            float t0 = 0.f;
            #pragma unroll
            for (int z4 = 0; z4 < 6; z4++) {
                float4 e = __ldg(ep + z4);
                t0 += e.x*er_r[4*z4] + e.y*er_r[4*z4+1] + e.z*er_r[4*z4+2] + e.w*er_r[4*z4+3];
            }
            acc = fmaf(t0, c, acc);
        }
        sc_s[x*33 + s] = logf(fmaxf(acc, EPSV)) + ml_s[s] + mr_s[s];
    }
    __syncthreads();
    if (tid < Nn) {
        float m = -3.4e38f;
        for (int s = 0; s < S; s++) m = fmaxf(m, sc_s[tid*33 + s]);
        float sum = 0.f;
        for (int s = 0; s < S; s++) sum += expf(sc_s[tid*33 + s] - m);
        g_beta[bidx(b, tid, i, j)] = m + logf(sum) + g_tm;
    }
}

// ---------------- outside cL step ----------------
__global__ void outL_kernel(int l) {
    __shared__ float erb_s[Nn*33];
    __shared__ float mrb_s[32];
    __shared__ float ea_s[Nn];
    __shared__ float ma_s;
    int tid = threadIdx.x;               // 128
    int i = blockIdx.x, b = blockIdx.y;
    int S = l - 1, j = i + l - 1;

    for (int t = tid; t < Nn*S; t += 128) {
        int z = t % Nn, s = t / Nn;
        erb_s[z*33 + s] = g_beta[bidx(b, z, i+s+1, j)];
    }
    if (tid < Nn) ea_s[tid] = g_alpha[bidx(b, tid, i, j)];
    __syncthreads();
    if (tid == 0) {
        float m = -3.4e38f;
        #pragma unroll
        for (int x = 0; x < Nn; x++) m = fmaxf(m, ea_s[x]);
        ma_s = m;
    }
    if (tid >= 32 && tid - 32 < S) {
        int s = tid - 32;
        float m = -3.4e38f;
        #pragma unroll
        for (int z = 0; z < Nn; z++) m = fmaxf(m, erb_s[z*33 + s]);
        mrb_s[s] = m;
        #pragma unroll
        for (int z = 0; z < Nn; z++) erb_s[z*33 + s] = expf(erb_s[z*33 + s] - m);
    }
    __syncthreads();
    float ma = ma_s;
    if (tid < Nn) ea_s[tid] = expf(ea_s[tid] - ma);
    __syncthreads();
    float tm = g_tm;

    for (int it = tid; it < Nn*S; it += 128) {
        int y = it / S, s = it - y*S;
        float erb_r[Nn];
        #pragma unroll
        for (int z = 0; z < Nn; z++) erb_r[z] = erb_s[z*33 + s];
        float acc = 0.f;
        #pragma unroll
        for (int x = 0; x < Nn; x++) {
            float c = ea_s[x];
            const float4* ep = reinterpret_cast<const float4*>(g_etY + (y*Nn + x)*Nn);
            float t0 = 0.f;
            #pragma unroll
            for (int z4 = 0; z4 < 6; z4++) {
                float4 e = __ldg(ep + z4);
                t0 += e.x*erb_r[4*z4] + e.y*erb_r[4*z4+1] + e.z*erb_r[4*z4+2] + e.w*erb_r[4*z4+3];
            }
            acc = fmaf(t0, c, acc);
        }
        float val = logf(fmaxf(acc, EPSV)) + tm + ma + mrb_s[s];
        int cell = bidx(b, y, i, i+s);
        float old = g_alpha[cell];
        float mx = fmaxf(old, val), mn = fminf(old, val);
        g_alpha[cell] = mx + log1pf(expf(mn - mx));
    }
}

// ---------------- outside cR step ----------------
__global__ void outR_kernel(int l) {
    __shared__ float elb_s[Nn*33];
    __shared__ float mlb_s[32];
    __shared__ float ea_s[Nn];
    __shared__ float ma_s;
    int tid = threadIdx.x;               // 128
    int i = blockIdx.x, b = blockIdx.y;
    int S = l - 1, j = i + l - 1;

    for (int t = tid; t < Nn*S; t += 128) {
        int y = t % Nn, s = t / Nn;
        elb_s[y*33 + s] = g_beta[bidx(b, y, i, i+s)];
    }
    if (tid < Nn) ea_s[tid] = g_alpha[bidx(b, tid, i, j)];
    __syncthreads();
    if (tid == 0) {
        float m = -3.4e38f;
        #pragma unroll
        for (int x = 0; x < Nn; x++) m = fmaxf(m, ea_s[x]);
        ma_s = m;
    }
    if (tid >= 32 && tid - 32 < S) {
        int s = tid - 32;
        float m = -3.4e38f;
        #pragma unroll
        for (int y = 0; y < Nn; y++) m = fmaxf(m, elb_s[y*33 + s]);
        mlb_s[s] = m;
        #pragma unroll
        for (int y = 0; y < Nn; y++) elb_s[y*33 + s] = expf(elb_s[y*33 + s] - m);
    }
    __syncthreads();
    float ma = ma_s;
    if (tid < Nn) ea_s[tid] = expf(ea_s[tid] - ma);
    __syncthreads();
    float tm = g_tm;

    for (int it = tid; it < Nn*S; it += 128) {
        int z = it / S, s = it - z*S;
        float elb_r[Nn];
        #pragma unroll
        for (int y = 0; y < Nn; y++) elb_r[y] = elb_s[y*33 + s];
        float acc = 0.f;
        #pragma unroll
        for (int x = 0; x < Nn; x++) {
            float c = ea_s[x];
            const float4* ep = reinterpret_cast<const float4*>(g_etZ + (z*Nn + x)*Nn);
            float t0 = 0.f;
            #pragma unroll
            for (int y4 = 0; y4 < 6; y4++) {
                float4 e = __ldg(ep + y4);
                t0 += e.x*elb_r[4*y4] + e.y*elb_r[4*y4+1] + e.z*elb_r[4*y4+2] + e.w*elb_r[4*y4+3];
            }
            acc = fmaf(t0, c, acc);
        }
        float val = logf(fmaxf(acc, EPSV)) + tm + ma + mlb_s[s];
        int cell = bidx(b, z, i+s+1, j);
        float old = g_alpha[cell];
        float mx = fmaxf(old, val), mn = fminf(old, val);
        g_alpha[cell] = mx + log1pf(expf(mn - mx));
    }
}

// ---------------- p_nt ----------------
__global__ void pnt_kernel() {
    int b = blockIdx.x;
    int tid = threadIdx.x;               // 768 = 24*32
    int n = tid / Tt, t = tid % Tt;
    float logZ = g_beta[bidx(b, 0, 0, Tt-1)];
    int d = bidx(b, n, t, t);
    g_pnt[(b*Tt + t)*Nn + n] = expf(g_alpha[d] + g_beta[d] - logZ);
}

// ---------------- L_pcfg scalar ----------------
__global__ void lpcfg_kernel(float* __restrict__ out) {
    int tid = threadIdx.x;               // 32
    float v = (tid < Bx) ? g_beta[bidx(tid, 0, 0, Tt-1)] : 0.f;
    #pragma unroll
    for (int off = 16; off > 0; off >>= 1) v += __shfl_xor_sync(0xffffffffu, v, off);
    if (tid == 0) out[(long long)Bx*Tt*Vv] = -v / (float)Bx;
}

// ---------------- mask_logits epilogue ----------------
__global__ void mask_kernel(const float* __restrict__ voc, float* __restrict__ out) {
    extern __shared__ float sm[];
    float* voc_s = sm;                   // 24*128
    float* pn_s  = sm + Nn*128;          // 512*24
    int tid = threadIdx.x;               // 256
    int v0 = blockIdx.x * 128;

    for (int t = tid; t < Bx*Tt*Nn; t += 256) pn_s[t] = g_pnt[t];
    for (int t = tid; t < Nn*128; t += 256) {
        int n = t >> 7, vl = t & 127;
        voc_s[t] = voc[n*Vv + v0 + vl];
    }
    __syncthreads();

    int vl = tid & 127;
    int v = v0 + vl;
    for (int bt = tid >> 7; bt < Bx*Tt; bt += 2) {
        float acc = 1e-6f;
        const float* p = pn_s + bt*Nn;
        #pragma unroll
        for (int n = 0; n < Nn; n++) acc = fmaf(p[n], voc_s[n*128 + vl], acc);
        out[(long long)bt*Vv + v] = logf(acc);
    }
}

// ---------------- launch ----------------
extern "C" void kernel_launch(void* const* d_in, const int* in_sizes, int n_in,
                              void* d_out, int out_size) {
    const float* g_seq   = (const float*)d_in[0];
    const float* Theta   = (const float*)d_in[1];
    const float* nt2voc  = (const float*)d_in[2];
    const float* ln_g    = (const float*)d_in[3];
    const float* ln_b    = (const float*)d_in[4];
    const float* W1      = (const float*)d_in[5];
    const float* b1      = (const float*)d_in[6];
    const float* W2      = (const float*)d_in[7];
    const float* b2      = (const float*)d_in[8];
    float* out = (float*)d_out;

    const int MASK_SMEM = (Nn*128 + Bx*Tt*Nn) * 4;   // 61440 B
    cudaFuncSetAttribute(mask_kernel, cudaFuncAttributeMaxDynamicSharedMemorySize, MASK_SMEM);

    fill_kernel<<<(Bx*Nn*Tt*Tt + 255)/256, 256>>>();
    theta_kernel<<<1, 576>>>(Theta);
    frontend_kernel<<<dim3(Tt, Bx), 128>>>(g_seq, ln_g, ln_b, W1, b1, W2, b2);

    for (int l = 2; l <= Tt; l++) {
        inside_kernel<<<dim3(Tt - l + 1, Bx), 128>>>(l);
    }
    for (int l = Tt; l >= 2; l--) {
        outL_kernel<<<dim3(Tt - l + 1, Bx), 128>>>(l);
        outR_kernel<<<dim3(Tt - l + 1, Bx), 128>>>(l);
    }

    pnt_kernel<<<Bx, Nn*Tt>>>();
    lpcfg_kernel<<<1, 32>>>(out);
    mask_kernel<<<Vv/128, 256, MASK_SMEM>>>(nt2voc, out);
}

// round 2
// speedup vs baseline: 2.2997x; 2.2997x over previous
#include <cuda_runtime.h>
#include <math.h>

#define Bx 16
#define Tt 32
#define Nn 24
#define Kk 512
#define Hh 128
#define Vv 32000
#define NEGV -1000000000.0f
#define EPSV 1e-38f

#define GRID 148
#define NT 768
#define ETN (Nn*Nn*Nn)
#define CMAX 48

// ---------------- device scratch ----------------
__device__ __align__(16) float g_beta[Bx*Nn*Tt*Tt];
__device__ __align__(16) float g_alpha[Bx*Nn*Tt*Tt];
__device__ __align__(16) float g_et [ETN];   // [x][y][z]
__device__ __align__(16) float g_etZ[ETN];   // [z][x][y]
__device__ float g_tm;
__device__ __align__(16) float g_pnt[Bx*Tt*Nn];
__device__ unsigned g_cnt;
__device__ unsigned g_flag;

__device__ __forceinline__ int bidx(int b, int n, int i, int j) {
    return ((b*Nn + n)*Tt + i)*Tt + j;
}

// ---------------- init ----------------
__global__ void fill_kernel() {
    int idx = blockIdx.x*blockDim.x + threadIdx.x;
    if (idx == 0) { g_cnt = 0u; g_flag = 0u; }
    if (idx < Bx*Nn*Tt*Tt) {
        g_beta[idx] = NEGV;
        int j = idx & 31;
        int i = (idx >> 5) & 31;
        int n = (idx >> 10) % Nn;
        g_alpha[idx] = (n == 0 && i == 0 && j == Tt-1) ? 0.0f : NEGV;
    }
}

// ---------------- theta prep ----------------
__global__ void theta_kernel(const float* __restrict__ Theta) {
    __shared__ float wmax[18];
    __shared__ float tm_s;
    int tid = threadIdx.x;              // 576
    const float* row = Theta + tid*Nn;
    float m = -3.4e38f;
    #pragma unroll
    for (int z = 0; z < Nn; z++) m = fmaxf(m, row[z]);
    float s = 0.f;
    #pragma unroll
    for (int z = 0; z < Nn; z++) s += expf(row[z] - m);
    float L = m + logf(s);
    float rm = m - L;
    #pragma unroll
    for (int off = 16; off > 0; off >>= 1)
        rm = fmaxf(rm, __shfl_xor_sync(0xffffffffu, rm, off));
    if ((tid & 31) == 0) wmax[tid >> 5] = rm;
    __syncthreads();
    if (tid == 0) {
        float t = -3.4e38f;
        for (int w = 0; w < 18; w++) t = fmaxf(t, wmax[w]);
        tm_s = t; g_tm = t;
    }
    __syncthreads();
    float tm = tm_s;
    int x = tid / Nn, y = tid % Nn;
    for (int z = 0; z < Nn; z++) {
        float e = expf(row[z] - L - tm);
        g_et [(x*Nn + y)*Nn + z] = e;
        g_etZ[(z*Nn + x)*Nn + y] = e;
    }
}

// ---------------- frontend ----------------
__global__ void frontend_kernel(const float* __restrict__ g_seq,
                                const float* __restrict__ ln_g,
                                const float* __restrict__ ln_b,
                                const float* __restrict__ W1,
                                const float* __restrict__ b1,
                                const float* __restrict__ W2,
                                const float* __restrict__ b2) {
    __shared__ float gs[Kk];
    __shared__ float red[Hh];
    __shared__ float hs[Hh];
    __shared__ float outs[Nn];
    int tid = threadIdx.x;              // 128
    int t = blockIdx.x, b = blockIdx.y;
    const float* row = g_seq + (b*Tt + t)*Kk;

    float v0 = row[tid], v1 = row[tid+128], v2 = row[tid+256], v3 = row[tid+384];
    gs[tid] = v0; gs[tid+128] = v1; gs[tid+256] = v2; gs[tid+384] = v3;

    red[tid] = v0+v1+v2+v3; __syncthreads();
    for (int off = 64; off > 0; off >>= 1) { if (tid < off) red[tid] += red[tid+off]; __syncthreads(); }
    float mu = red[0] * (1.f/512.f);
    __syncthreads();
    red[tid] = v0*v0 + v1*v1 + v2*v2 + v3*v3; __syncthreads();
    for (int off = 64; off > 0; off >>= 1) { if (tid < off) red[tid] += red[tid+off]; __syncthreads(); }
    float var = red[0] * (1.f/512.f) - mu*mu;
    float rstd = rsqrtf(var + 1e-5f);
    __syncthreads();

    #pragma unroll
    for (int q = 0; q < 4; q++) {
        int k = tid + q*128;
        gs[k] = (gs[k] - mu) * rstd * ln_g[k] + ln_b[k];
    }
    __syncthreads();

    float acc = b1[tid];
    for (int k = 0; k < Kk; k++) acc = fmaf(gs[k], W1[k*Hh + tid], acc);
    hs[tid] = 0.5f * acc * (1.0f + erff(acc * 0.70710678118654752440f));
    __syncthreads();

    if (tid < Nn) {
        float o = b2[tid];
        for (int m2 = 0; m2 < Hh; m2++) o = fmaf(hs[m2], W2[m2*Nn + tid], o);
        outs[tid] = o;
    }
    __syncthreads();
    if (tid < Nn) {
        float m = -3.4e38f;
        #pragma unroll
        for (int n = 0; n < Nn; n++) m = fmaxf(m, outs[n]);
        float s = 0.f;
        #pragma unroll
        for (int n = 0; n < Nn; n++) s += expf(outs[n] - m);
        g_beta[bidx(b, tid, t, t)] = outs[tid] - m - logf(s);
    }
}

// ---------------- grid barrier (software, safe: grid <= #SM, 1 block/SM) ----------------
__device__ __forceinline__ void grid_barrier(unsigned gen) {
    __syncthreads();
    if (threadIdx.x == 0) {
        __threadfence();
        unsigned prev = atomicAdd(&g_cnt, 1u);
        if (prev == gen*GRID - 1u) {
            atomicExch(&g_flag, gen);
        } else {
            while (atomicAdd(&g_flag, 0u) < gen) __nanosleep(64);
        }
        __threadfence();
    }
    __syncthreads();
}

// ---------------- fused DP kernel: inside + outside ----------------
__global__ void __launch_bounds__(NT, 1) dp_kernel() {
    extern __shared__ float sm[];
    float* s_et  = sm;                    // 13824
    float* s_etZ = s_et + ETN;            // 13824
    float* sA    = s_etZ + ETN;           // 24*CMAX  (el / elb)
    float* sB    = sA + Nn*CMAX;          // 24*CMAX  (er / erb)
    float* sC    = sB + Nn*CMAX;          // 24*CMAX  (sc)
    float* mA    = sC + Nn*CMAX;          // CMAX (ml / mrb / mlb)
    float* mB    = mA + CMAX;             // CMAX (mr)
    float* sEA   = mB + CMAX;             // 4*24 exp'd parent alpha rows
    float* sMA   = sEA + 4*Nn;            // 4 parent maxima

    int tid = threadIdx.x;
    int bk  = blockIdx.x;

    for (int t = tid; t < ETN; t += NT) { s_et[t] = g_et[t]; s_etZ[t] = g_etZ[t]; }
    __syncthreads();
    float tm = g_tm;
    unsigned bar = 0;

    // ================= INSIDE =================
    for (int l = 2; l <= Tt; l++) {
        int P = Tt - l + 1, S = l - 1;
        int units = Bx * P;
        int q = units / GRID, r = units % GRID;
        int Ublk = q + (bk < r ? 1 : 0);
        int base = bk*q + (bk < r ? bk : r);
        int C = Ublk * S;
        if (Ublk > 0) {
            // stage tiles
            for (int t = tid; t < Nn*C; t += NT) {
                int y = t / C, c = t - y*C;
                int u = c / S, s = c - u*S;
                int gu = base + u; int b = gu / P, i = gu - b*P;
                sA[y*C + c] = g_beta[bidx(b, y, i, i+s)];
                sB[y*C + c] = g_beta[bidx(b, y, i+s+1, i+l-1)];
            }
            __syncthreads();
            // per-column max + exp
            for (int c = tid; c < C; c += NT) {
                float m = -3.4e38f;
                #pragma unroll
                for (int y = 0; y < Nn; y++) m = fmaxf(m, sA[y*C + c]);
                mA[c] = m;
                #pragma unroll
                for (int y = 0; y < Nn; y++) sA[y*C + c] = expf(sA[y*C + c] - m);
                m = -3.4e38f;
                #pragma unroll
                for (int y = 0; y < Nn; y++) m = fmaxf(m, sB[y*C + c]);
                mB[c] = m;
                #pragma unroll
                for (int y = 0; y < Nn; y++) sB[y*C + c] = expf(sB[y*C + c] - m);
            }
            __syncthreads();
            // bilinear contraction items
            for (int it = tid; it < Nn*C; it += NT) {
                int x = it / C, c = it - x*C;
                float er_r[Nn];
                #pragma unroll
                for (int z = 0; z < Nn; z++) er_r[z] = sB[z*C + c];
                float acc = 0.f;
                const float4* et4 = reinterpret_cast<const float4*>(s_et + x*Nn*Nn);
                #pragma unroll 6
                for (int y = 0; y < Nn; y++) {
                    float t0 = 0.f, t1 = 0.f;
                    #pragma unroll
                    for (int q4 = 0; q4 < 6; q4++) {
                        float4 e = et4[y*6 + q4];
                        t0 += e.x*er_r[4*q4]   + e.y*er_r[4*q4+1];
                        t1 += e.z*er_r[4*q4+2] + e.w*er_r[4*q4+3];
                    }
                    acc = fmaf(sA[y*C + c], t0 + t1, acc);
                }
                sC[x*C + c] = logf(fmaxf(acc, EPSV)) + mA[c] + mB[c];
            }
            __syncthreads();
            // logsumexp over splits -> beta
            for (int t = tid; t < Ublk*Nn; t += NT) {
                int u = t / Nn, x = t - u*Nn;
                int gu = base + u; int b = gu / P, i = gu - b*P;
                float m = -3.4e38f;
                for (int s = 0; s < S; s++) m = fmaxf(m, sC[x*C + u*S + s]);
                float sum = 0.f;
                for (int s = 0; s < S; s++) sum += expf(sC[x*C + u*S + s] - m);
                g_beta[bidx(b, x, i, i+l-1)] = m + logf(sum) + tm;
            }
        }
        grid_barrier(++bar);
    }

    // ================= OUTSIDE =================
    for (int l = Tt; l >= 2; l--) {
        int P = Tt - l + 1, S = l - 1;
        int units = Bx * P;
        int q = units / GRID, r = units % GRID;
        int Ublk = q + (bk < r ? 1 : 0);
        int base = bk*q + (bk < r ? bk : r);
        int C = Ublk * S;

        // ---- cL phase ----
        if (Ublk > 0) {
            for (int t = tid; t < Nn*C; t += NT) {
                int z = t / C, c = t - z*C;
                int u = c / S, s = c - u*S;
                int gu = base + u; int b = gu / P, i = gu - b*P;
                sB[z*C + c] = g_beta[bidx(b, z, i+s+1, i+l-1)];
            }
            if (tid < Ublk*Nn) {
                int u = tid / Nn, x = tid - u*Nn;
                int gu = base + u; int b = gu / P, i = gu - b*P;
                sEA[u*Nn + x] = g_alpha[bidx(b, x, i, i+l-1)];
            }
            __syncthreads();
            for (int c = tid; c < C; c += NT) {
                float m = -3.4e38f;
                #pragma unroll
                for (int z = 0; z < Nn; z++) m = fmaxf(m, sB[z*C + c]);
                mA[c] = m;
                #pragma unroll
                for (int z = 0; z < Nn; z++) sB[z*C + c] = expf(sB[z*C + c] - m);
            }
            if (tid < Ublk) {
                float m = -3.4e38f;
                #pragma unroll
                for (int x = 0; x < Nn; x++) m = fmaxf(m, sEA[tid*Nn + x]);
                sMA[tid] = m;
                #pragma unroll
                for (int x = 0; x < Nn; x++) sEA[tid*Nn + x] = expf(sEA[tid*Nn + x] - m);
            }
            __syncthreads();
            for (int it = tid; it < Nn*C; it += NT) {
                int y = it / C, c = it - y*C;
                int u = c / S, s = c - u*S;
                float erb_r[Nn];
                #pragma unroll
                for (int z = 0; z < Nn; z++) erb_r[z] = sB[z*C + c];
                float acc = 0.f;
                #pragma unroll 6
                for (int x = 0; x < Nn; x++) {
                    const float4* row4 = reinterpret_cast<const float4*>(s_et + (x*Nn + y)*Nn);
                    float t0 = 0.f, t1 = 0.f;
                    #pragma unroll
                    for (int q4 = 0; q4 < 6; q4++) {
                        float4 e = row4[q4];
                        t0 += e.x*erb_r[4*q4]   + e.y*erb_r[4*q4+1];
                        t1 += e.z*erb_r[4*q4+2] + e.w*erb_r[4*q4+3];
                    }
                    acc = fmaf(sEA[u*Nn + x], t0 + t1, acc);
                }
                int gu = base + u; int b = gu / P, i = gu - b*P;
                float val = logf(fmaxf(acc, EPSV)) + tm + sMA[u] + mA[c];
                int cell = bidx(b, y, i, i+s);
                float old = g_alpha[cell];
                float mx = fmaxf(old, val), mn = fminf(old, val);
                g_alpha[cell] = mx + log1pf(expf(mn - mx));
            }
        }
        grid_barrier(++bar);

        // ---- cR phase ----
        if (Ublk > 0) {
            for (int t = tid; t < Nn*C; t += NT) {
                int y = t / C, c = t - y*C;
                int u = c / S, s = c - u*S;
                int gu = base + u; int b = gu / P, i = gu - b*P;
                sA[y*C + c] = g_beta[bidx(b, y, i, i+s)];
            }
            if (tid < Ublk*Nn) {
                int u = tid / Nn, x = tid - u*Nn;
                int gu = base + u; int b = gu / P, i = gu - b*P;
                sEA[u*Nn + x] = g_alpha[bidx(b, x, i, i+l-1)];
            }
            __syncthreads();
            for (int c = tid; c < C; c += NT) {
                float m = -3.4e38f;
                #pragma unroll
                for (int y = 0; y < Nn; y++) m = fmaxf(m, sA[y*C + c]);
                mA[c] = m;
                #pragma unroll
                for (int y = 0; y < Nn; y++) sA[y*C + c] = expf(sA[y*C + c] - m);
            }
            if (tid < Ublk) {
                float m = -3.4e38f;
                #pragma unroll
                for (int x = 0; x < Nn; x++) m = fmaxf(m, sEA[tid*Nn + x]);
                sMA[tid] = m;
                #pragma unroll
                for (int x = 0; x < Nn; x++) sEA[tid*Nn + x] = expf(sEA[tid*Nn + x] - m);
            }
            __syncthreads();
            for (int it = tid; it < Nn*C; it += NT) {
                int z = it / C, c = it - z*C;
                int u = c / S, s = c - u*S;
                float elb_r[Nn];
                #pragma unroll
                for (int y = 0; y < Nn; y++) elb_r[y] = sA[y*C + c];
                float acc = 0.f;
                const float4* etz4 = reinterpret_cast<const float4*>(s_etZ + z*Nn*Nn);
                #pragma unroll 6
                for (int x = 0; x < Nn; x++) {
                    float t0 = 0.f, t1 = 0.f;
                    #pragma unroll
                    for (int q4 = 0; q4 < 6; q4++) {
                        float4 e = etz4[x*6 + q4];
                        t0 += e.x*elb_r[4*q4]   + e.y*elb_r[4*q4+1];
                        t1 += e.z*elb_r[4*q4+2] + e.w*elb_r[4*q4+3];
                    }
                    acc = fmaf(sEA[u*Nn + x], t0 + t1, acc);
                }
                int gu = base + u; int b = gu / P, i = gu - b*P;
                float val = logf(fmaxf(acc, EPSV)) + tm + sMA[u] + mA[c];
                int cell = bidx(b, z, i+s+1, i+l-1);
                float old = g_alpha[cell];
                float mx = fmaxf(old, val), mn = fminf(old, val);
                g_alpha[cell] = mx + log1pf(expf(mn - mx));
            }
        }
        grid_barrier(++bar);
    }
}

// ---------------- p_nt ----------------
__global__ void pnt_kernel() {
    int b = blockIdx.x;
    int tid = threadIdx.x;               // 768
    int n = tid / Tt, t = tid % Tt;
    float logZ = g_beta[bidx(b, 0, 0, Tt-1)];
    int d = bidx(b, n, t, t);
    g_pnt[(b*Tt + t)*Nn + n] = expf(g_alpha[d] + g_beta[d] - logZ);
}

// ---------------- L_pcfg ----------------
__global__ void lpcfg_kernel(float* __restrict__ out) {
    int tid = threadIdx.x;               // 32
    float v = (tid < Bx) ? g_beta[bidx(tid, 0, 0, Tt-1)] : 0.f;
    #pragma unroll
    for (int off = 16; off > 0; off >>= 1) v += __shfl_xor_sync(0xffffffffu, v, off);
    if (tid == 0) out[(long long)Bx*Tt*Vv] = -v / (float)Bx;
}

// ---------------- mask_logits ----------------
__global__ void mask_kernel(const float* __restrict__ voc, float* __restrict__ out) {
    extern __shared__ float sm[];
    float* voc_s = sm;                   // 24*128
    float* pn_s  = sm + Nn*128;          // 512*24
    int tid = threadIdx.x;               // 256
    int v0 = blockIdx.x * 128;

    for (int t = tid; t < Bx*Tt*Nn; t += 256) pn_s[t] = g_pnt[t];
    for (int t = tid; t < Nn*128; t += 256) {
        int n = t >> 7, vl = t & 127;
        voc_s[t] = voc[n*Vv + v0 + vl];
    }
    __syncthreads();

    int vl = tid & 127;
    int v = v0 + vl;
    for (int bt = tid >> 7; bt < Bx*Tt; bt += 2) {
        float acc = 1e-6f;
        const float* p = pn_s + bt*Nn;
        #pragma unroll
        for (int n = 0; n < Nn; n++) acc = fmaf(p[n], voc_s[n*128 + vl], acc);
        out[(long long)bt*Vv + v] = logf(acc);
    }
}

// ---------------- launch ----------------
extern "C" void kernel_launch(void* const* d_in, const int* in_sizes, int n_in,
                              void* d_out, int out_size) {
    const float* g_seq   = (const float*)d_in[0];
    const float* Theta   = (const float*)d_in[1];
    const float* nt2voc  = (const float*)d_in[2];
    const float* ln_g    = (const float*)d_in[3];
    const float* ln_b    = (const float*)d_in[4];
    const float* W1      = (const float*)d_in[5];
    const float* b1      = (const float*)d_in[6];
    const float* W2      = (const float*)d_in[7];
    const float* b2      = (const float*)d_in[8];
    float* out = (float*)d_out;

    const int MASK_SMEM = (Nn*128 + Bx*Tt*Nn) * 4;
    const int DP_SMEM   = (2*ETN + 3*Nn*CMAX + 2*CMAX + 4*Nn + 4) * 4;
    cudaFuncSetAttribute(mask_kernel, cudaFuncAttributeMaxDynamicSharedMemorySize, MASK_SMEM);
    cudaFuncSetAttribute(dp_kernel,   cudaFuncAttributeMaxDynamicSharedMemorySize, DP_SMEM);

    fill_kernel<<<(Bx*Nn*Tt*Tt + 255)/256, 256>>>();
    theta_kernel<<<1, 576>>>(Theta);
    frontend_kernel<<<dim3(Tt, Bx), 128>>>(g_seq, ln_g, ln_b, W1, b1, W2, b2);

    dp_kernel<<<GRID, NT, DP_SMEM>>>();

    pnt_kernel<<<Bx, Nn*Tt>>>();
    lpcfg_kernel<<<1, 32>>>(out);
    mask_kernel<<<Vv/128, 256, MASK_SMEM>>>(nt2voc, out);
}